// round 8
// baseline (speedup 1.0000x reference)
#include <cuda_runtime.h>
#include <stdint.h>

#define NN    2048
#define BSZ   16
#define NEGINF (-1e30f)

// ---------------- device scratch (static globals; no runtime allocation) ----
static __device__ float g_at[BSZ];
static __device__ float g_sc[BSZ];
static __device__ float g_csx[BSZ * 32];
static __device__ float g_csy[BSZ * 32];
static __device__ float g_biasB[BSZ * 64];
static __device__ __align__(16) float g_Wb[BSZ * 96 * 64];
static __device__ __align__(16) float g_Wn[NN * 96 * 64];     // 50.3 MB
static __device__ float g_unif[BSZ * NN];
static __device__ float g_w[BSZ * NN * 10];
static __device__ int   g_sidx[BSZ * NN * 10];
static __device__ __align__(16) float g_y1[BSZ * NN * 32];
static __device__ __align__(16) float g_y2[BSZ * NN * 32];

// ---------------- bit-exact threefry-2x32-20, key = (0, 42) -----------------
__device__ __forceinline__ void threefry_0_42(uint32_t x0, uint32_t x1,
                                              uint32_t& o0, uint32_t& o1) {
    const uint32_t ks0 = 0u, ks1 = 42u, ks2 = 0x1BD11BF0u; // 0^42^0x1BD11BDA
    x0 += ks0; x1 += ks1;
#define TF_R(r) { x0 += x1; x1 = (x1 << (r)) | (x1 >> (32 - (r))); x1 ^= x0; }
    TF_R(13) TF_R(15) TF_R(26) TF_R(6)   x0 += ks1; x1 += ks2 + 1u;
    TF_R(17) TF_R(29) TF_R(16) TF_R(24)  x0 += ks2; x1 += ks0 + 2u;
    TF_R(13) TF_R(15) TF_R(26) TF_R(6)   x0 += ks0; x1 += ks1 + 3u;
    TF_R(17) TF_R(29) TF_R(16) TF_R(24)  x0 += ks1; x1 += ks2 + 4u;
    TF_R(13) TF_R(15) TF_R(26) TF_R(6)   x0 += ks2; x1 += ks0 + 5u;
#undef TF_R
    o0 = x0; o1 = x1;
}

// Partitionable threefry (verified R6): counter = (0, e), bits = o0 ^ o1.
__device__ __forceinline__ float jax_noise(uint32_t e) {
    uint32_t o0, o1;
    threefry_0_42(0u, e, o0, o1);
    uint32_t bits = o0 ^ o1;
    float u = __uint_as_float((bits >> 9) | 0x3f800000u) - 1.0f;
    return __fmul_rn(u, 0.01f);
}

// ---------------- K1: per-batch scalars, biasB, Wb ---------------------------
__global__ void k_prep(const float* __restrict__ t, const float* __restrict__ nt,
                       const float* __restrict__ p, const float* __restrict__ wp,
                       const float* __restrict__ bp) {
    int b = blockIdx.x, tid = threadIdx.x;
    __shared__ float snt[8];
    if (tid < 8) snt[tid] = nt[b * 8 + tid];
    __syncthreads();
    if (tid == 0) {
        float at = 0.f;
        for (int d = 0; d < 8; d++) at += snt[d] * t[b * 8 + d];
        g_at[b] = at;
        float pv = p[b];
        g_sc[b] = 1.f + 0.3f * (1.f / (1.f + expf(-pv)));
    }
    float acc = 0.f;
#pragma unroll
    for (int d = 0; d < 8; d++) acc += snt[d] * bp[(10 + d) * 64 + tid];
    g_biasB[b * 64 + tid] = acc;
    for (int ki = 0; ki < 96; ki++) {
        float a2 = 0.f;
#pragma unroll
        for (int d = 0; d < 8; d++) a2 += snt[d] * wp[(10 + d) * 6144 + ki * 64 + tid];
        g_Wb[b * 6144 + ki * 64 + tid] = a2;
    }
}

// ---------------- K2/K6: column sums over nodes ------------------------------
__global__ void k_colsum(const float* __restrict__ src, float* __restrict__ dst) {
    int b = blockIdx.x, tid = threadIdx.x;
    int c = tid & 31, r0 = tid >> 5;
    float acc = 0.f;
    for (int n = r0; n < NN; n += 8) acc += src[(b * NN + n) * 32 + c];
    __shared__ float sm[256];
    sm[tid] = acc;
    __syncthreads();
    if (tid < 32) {
        float a = sm[tid];
#pragma unroll
        for (int g = 1; g < 8; g++) a += sm[g * 32 + tid];
        dst[b * 32 + tid] = a;
    }
}

// ---------------- K3: Wn = node_emb @ wp[:10]  (skinny GEMM) -----------------
__global__ __launch_bounds__(256) void k_wn(const float* __restrict__ ne,
                                            const float* __restrict__ wp) {
    int tid = threadIdx.x;
    int col = blockIdx.y * 256 + tid;          // 0..6143
    int n0 = blockIdx.x * 16;
    __shared__ float wps[10 * 256];
    __shared__ float nes[16 * 10];
#pragma unroll
    for (int d = 0; d < 10; d++) wps[d * 256 + tid] = wp[d * 6144 + col];
    if (tid < 160) nes[tid] = ne[n0 * 10 + tid];
    __syncthreads();
    for (int nn = 0; nn < 16; nn++) {
        float acc = 0.f;
#pragma unroll
        for (int d = 0; d < 10; d++) acc += nes[nn * 10 + d] * wps[d * 256 + tid];
        g_Wn[(n0 + nn) * 6144 + col] = acc;
    }
}

// ---------------- K4: 8 rows per block; warp-local top16 + merge -------------
// dyn smem layout: s_neT[10][2048] (transposed node_emb), then candidate bufs
__global__ __launch_bounds__(256) void k_select(const float* __restrict__ ne) {
    extern __shared__ float sm[];
    float* s_neT = sm;                         // 10 * 2048
    float* s_wv  = sm + 20480;                 // 128 warp candidates (values)
    int*   s_wi  = (int*)(sm + 20480 + 128);   // 128 warp candidates (indices)
    float* s_cv  = sm + 20480 + 256;           // 16 merged values
    int*   s_ci  = (int*)(sm + 20480 + 272);   // 16 merged indices

    int tid = threadIdx.x, lane = tid & 31, w = tid >> 5;

    // stage node_emb transposed (coalesced global reads)
    for (int m = tid; m < NN * 10; m += 256) {
        int r = m / 10, d = m - r * 10;
        s_neT[d * NN + r] = ne[m];
    }
    __syncthreads();

    for (int ii = 0; ii < 8; ii++) {
        int i = blockIdx.x * 8 + ii;

        float nei[10];
#pragma unroll
        for (int d = 0; d < 10; d++) nei[d] = s_neT[d * NN + i];

        // each warp computes 256 dots into registers (identical fp32 order)
        int jbase = w * 256;
        float v[8];
#pragma unroll
        for (int q = 0; q < 8; q++) {
            int j = jbase + q * 32 + lane;
            float acc = 0.f;
#pragma unroll
            for (int d = 0; d < 10; d++) acc += nei[d] * s_neT[d * NN + j];
            v[q] = acc;
        }

        // warp-local top-16 (value desc, index asc on ties)
        for (int r = 0; r < 16; r++) {
            float bv = v[0]; int bq = 0;
#pragma unroll
            for (int q = 1; q < 8; q++) if (v[q] > bv) { bv = v[q]; bq = q; }
            int bj = jbase + bq * 32 + lane;
#pragma unroll
            for (int off = 16; off; off >>= 1) {
                float ov = __shfl_down_sync(0xffffffffu, bv, off);
                int   oj = __shfl_down_sync(0xffffffffu, bj, off);
                if (ov > bv || (ov == bv && oj < bj)) { bv = ov; bj = oj; }
            }
            bv = __shfl_sync(0xffffffffu, bv, 0);
            bj = __shfl_sync(0xffffffffu, bj, 0);
            if (lane == 0) { s_wv[w * 16 + r] = bv; s_wi[w * 16 + r] = bj; }
            if (lane == (bj & 31)) v[(bj >> 5) & 7] = NEGINF;
        }
        __syncthreads();

        // warp 0 merges 128 candidates -> global top-16 (sorted desc, idx asc)
        if (w == 0) {
            float mv[4]; int mi[4];
#pragma unroll
            for (int q = 0; q < 4; q++) {
                mv[q] = s_wv[q * 32 + lane];
                mi[q] = s_wi[q * 32 + lane];
            }
            for (int r = 0; r < 16; r++) {
                float bv = mv[0]; int bi = mi[0];
#pragma unroll
                for (int q = 1; q < 4; q++)
                    if (mv[q] > bv || (mv[q] == bv && mi[q] < bi)) { bv = mv[q]; bi = mi[q]; }
#pragma unroll
                for (int off = 16; off; off >>= 1) {
                    float ov = __shfl_down_sync(0xffffffffu, bv, off);
                    int   oi = __shfl_down_sync(0xffffffffu, bi, off);
                    if (ov > bv || (ov == bv && oi < bi)) { bv = ov; bi = oi; }
                }
                bv = __shfl_sync(0xffffffffu, bv, 0);
                bi = __shfl_sync(0xffffffffu, bi, 0);
                if (lane == 0) { s_cv[r] = bv; s_ci[r] = bi; }
#pragma unroll
                for (int q = 0; q < 4; q++) if (mi[q] == bi) mv[q] = NEGINF;
            }
        }
        __syncthreads();

        // per-batch: warp w handles batches w and w+8
        for (int bb = 0; bb < 2; bb++) {
            int b = w + bb * 8;
            float s = g_sc[b], at = g_at[b];
            float myv = 0.f, key = NEGINF;
            int cj = -1;
            if (lane < 16) {
                cj = s_ci[lane];
                float pre = s * (s_cv[lane] + at);
                myv = pre > 0.f ? pre : 0.f;
                uint32_t e = (uint32_t)b * 4194304u + (uint32_t)i * 2048u + (uint32_t)cj;
                key = __fadd_rn(myv, jax_noise(e));
            }
            // top-10 of 16 by key
            float kwork = key;
            bool sel = false;
#pragma unroll
            for (int r = 0; r < 10; r++) {
                float bv = kwork; int bl = lane;
#pragma unroll
                for (int off = 16; off; off >>= 1) {
                    float ov = __shfl_down_sync(0xffffffffu, bv, off);
                    int   ol = __shfl_down_sync(0xffffffffu, bl, off);
                    if (ov > bv) { bv = ov; bl = ol; }
                }
                bl = __shfl_sync(0xffffffffu, bl, 0);
                if (lane == bl) { sel = true; kwork = NEGINF; }
            }
            // softmax over 2048 entries: 10 selected values, 2038 zeros
            float mv2 = sel ? myv : NEGINF;
#pragma unroll
            for (int off = 16; off; off >>= 1)
                mv2 = fmaxf(mv2, __shfl_down_sync(0xffffffffu, mv2, off));
            float m = __shfl_sync(0xffffffffu, mv2, 0);
            float se = sel ? expf(myv - m) : 0.f;
            float ss = se;
#pragma unroll
            for (int off = 16; off; off >>= 1)
                ss += __shfl_down_sync(0xffffffffu, ss, off);
            ss = __shfl_sync(0xffffffffu, ss, 0);
            float eu = expf(-m);
            float Z = ss + 2038.f * eu;
            float unif = eu / Z;
            unsigned mask = __ballot_sync(0xffffffffu, sel);
            if (sel) {
                int pos = __popc(mask & ((1u << lane) - 1u));
                int base = (b * NN + i) * 10 + pos;
                g_sidx[base] = cj;
                g_w[base] = se / Z - unif;
            }
            if (lane == 0) g_unif[b * NN + i] = unif;
        }
        __syncthreads();
    }
}

// ---------------- K5/K7: y = A @ src (uniform + sparse); pass2: y=2y-x -------
__global__ __launch_bounds__(256) void k_spmv(const float* __restrict__ src,
                                              const float* __restrict__ cs,
                                              const float* __restrict__ x,
                                              float* __restrict__ dst, int pass2) {
    int lane = threadIdx.x & 31, w = threadIdx.x >> 5;
    int r = blockIdx.x * 8 + w;                  // r = b*2048 + n
    int b = r >> 11;
    float acc = g_unif[r] * cs[b * 32 + lane];
    const int*   id = g_sidx + r * 10;
    const float* ww = g_w + r * 10;
#pragma unroll
    for (int tt = 0; tt < 10; tt++)
        acc += ww[tt] * src[(b * NN + id[tt]) * 32 + lane];
    if (pass2) acc = 2.f * acc - x[r * 32 + lane];
    dst[r * 32 + lane] = acc;
}

// ---------------- K8: per-node term + biases (writes out) --------------------
__global__ __launch_bounds__(128) void k_out1(const float* __restrict__ x,
                                              const float* __restrict__ y1,
                                              const float* __restrict__ y2,
                                              const float* __restrict__ ne,
                                              const float* __restrict__ bp,
                                              float* __restrict__ out) {
    int n = blockIdx.x, tid = threadIdx.x;
    __shared__ float sW[6144];
    __shared__ float sx[16 * 96];
    __shared__ float sbp[640];
    __shared__ float snerow[10];
    for (int m = tid; m < 6144; m += 128) sW[m] = g_Wn[n * 6144 + m];
    for (int m = tid; m < 1536; m += 128) {
        int b = m / 96, k = m - b * 96;
        const float* src = (k < 32) ? x : (k < 64) ? y1 : y2;
        sx[m] = src[(b * NN + n) * 32 + (k & 31)];
    }
    for (int m = tid; m < 640; m += 128) sbp[m] = bp[m];
    if (tid < 10) snerow[tid] = ne[n * 10 + tid];
    __syncthreads();
    int o = tid & 63, g = tid >> 6;
    float acc[8] = {0, 0, 0, 0, 0, 0, 0, 0};
    for (int k = 0; k < 96; k++) {
        float wv = sW[k * 64 + o];
#pragma unroll
        for (int q = 0; q < 8; q++) acc[q] += sx[(g + 2 * q) * 96 + k] * wv;
    }
    float bn = 0.f;
#pragma unroll
    for (int d = 0; d < 10; d++) bn += snerow[d] * sbp[d * 64 + o];
#pragma unroll
    for (int q = 0; q < 8; q++) {
        int b = g + 2 * q;
        out[((b * NN) + n) * 64 + o] = acc[q] + bn + g_biasB[b * 64 + o];
    }
}

// ---------------- K9: per-batch GEMM term, accumulates into out --------------
__global__ __launch_bounds__(256) void k_out2(const float* __restrict__ x,
                                              const float* __restrict__ y1,
                                              const float* __restrict__ y2,
                                              float* __restrict__ out) {
    int n0 = blockIdx.x * 64, b = blockIdx.y, tid = threadIdx.x;
    __shared__ float sWb[48 * 64];
    __shared__ float sxg[64 * 97];
    {
        const float* srcs[3] = {x, y1, y2};
#pragma unroll
        for (int a = 0; a < 3; a++) {
            const float* s = srcs[a];
            for (int m = tid; m < 2048; m += 256) {
                int rr = m >> 5, c = m & 31;
                sxg[rr * 97 + a * 32 + c] = s[(b * NN + n0 + rr) * 32 + c];
            }
        }
    }
    int o0 = (tid & 15) * 4, tn = tid >> 4;
    float acc[4][4];
#pragma unroll
    for (int rr = 0; rr < 4; rr++)
#pragma unroll
        for (int oo = 0; oo < 4; oo++) acc[rr][oo] = 0.f;

    for (int kc = 0; kc < 2; kc++) {
        __syncthreads();
        for (int m = tid; m < 3072; m += 256)
            sWb[m] = g_Wb[b * 6144 + kc * 3072 + m];
        __syncthreads();
        for (int k = 0; k < 48; k++) {
            float4 wv = *(const float4*)&sWb[k * 64 + o0];
#pragma unroll
            for (int rr = 0; rr < 4; rr++) {
                float xv = sxg[(tn + 16 * rr) * 97 + kc * 48 + k];
                acc[rr][0] += xv * wv.x; acc[rr][1] += xv * wv.y;
                acc[rr][2] += xv * wv.z; acc[rr][3] += xv * wv.w;
            }
        }
    }
#pragma unroll
    for (int rr = 0; rr < 4; rr++) {
        int row = tn + 16 * rr;
        float4* op = (float4*)&out[((b * NN) + (n0 + row)) * 64 + o0];
        float4 cur = *op;
        cur.x += acc[rr][0]; cur.y += acc[rr][1];
        cur.z += acc[rr][2]; cur.w += acc[rr][3];
        *op = cur;
    }
}

// ---------------- launch ------------------------------------------------------
extern "C" void kernel_launch(void* const* d_in, const int* in_sizes, int n_in,
                              void* d_out, int out_size) {
    const float* x  = (const float*)d_in[0];
    const float* ne = (const float*)d_in[1];
    const float* t  = (const float*)d_in[2];
    const float* nt = (const float*)d_in[3];
    const float* p  = (const float*)d_in[4];
    const float* wp = (const float*)d_in[5];
    const float* bp = (const float*)d_in[6];
    float* out = (float*)d_out;

    float *y1, *y2, *csx, *csy;
    cudaGetSymbolAddress((void**)&y1, g_y1);
    cudaGetSymbolAddress((void**)&y2, g_y2);
    cudaGetSymbolAddress((void**)&csx, g_csx);
    cudaGetSymbolAddress((void**)&csy, g_csy);

    const int sel_smem = (20480 + 288) * 4;   // ~83KB dynamic shared
    cudaFuncSetAttribute(k_select, cudaFuncAttributeMaxDynamicSharedMemorySize, sel_smem);

    k_prep<<<BSZ, 64>>>(t, nt, p, wp, bp);
    k_colsum<<<BSZ, 256>>>(x, csx);
    k_wn<<<dim3(128, 24), 256>>>(ne, wp);
    k_select<<<NN / 8, 256, sel_smem>>>(ne);
    k_spmv<<<4096, 256>>>(x, csx, x, y1, 0);
    k_colsum<<<BSZ, 256>>>(y1, csy);
    k_spmv<<<4096, 256>>>(y1, csy, x, y2, 1);
    k_out1<<<NN, 128>>>(x, y1, y2, ne, bp, out);
    k_out2<<<dim3(32, BSZ), 256>>>(x, y1, y2, out);
}

// round 9
// speedup vs baseline: 1.5561x; 1.5561x over previous
#include <cuda_runtime.h>
#include <stdint.h>

#define NN    2048
#define BSZ   16
#define NEGINF (-1e30f)

// ---------------- device scratch (static globals; no runtime allocation) ----
static __device__ float g_at[BSZ];
static __device__ float g_sc[BSZ];
static __device__ float g_csx[BSZ * 8 * 32];   // partial colsums [b][g][c]
static __device__ float g_csy[BSZ * 8 * 32];
static __device__ float g_biasB[BSZ * 64];
static __device__ __align__(16) float g_Wb[BSZ * 96 * 64];
static __device__ __align__(16) float g_Wn[NN * 96 * 64];     // 50.3 MB
static __device__ float g_unif[BSZ * NN];
static __device__ float g_w[BSZ * NN * 10];
static __device__ int   g_sidx[BSZ * NN * 10];
static __device__ __align__(16) float g_y1[BSZ * NN * 32];
static __device__ __align__(16) float g_y2[BSZ * NN * 32];

// ---------------- bit-exact threefry-2x32-20, key = (0, 42) -----------------
__device__ __forceinline__ void threefry_0_42(uint32_t x0, uint32_t x1,
                                              uint32_t& o0, uint32_t& o1) {
    const uint32_t ks0 = 0u, ks1 = 42u, ks2 = 0x1BD11BF0u; // 0^42^0x1BD11BDA
    x0 += ks0; x1 += ks1;
#define TF_R(r) { x0 += x1; x1 = (x1 << (r)) | (x1 >> (32 - (r))); x1 ^= x0; }
    TF_R(13) TF_R(15) TF_R(26) TF_R(6)   x0 += ks1; x1 += ks2 + 1u;
    TF_R(17) TF_R(29) TF_R(16) TF_R(24)  x0 += ks2; x1 += ks0 + 2u;
    TF_R(13) TF_R(15) TF_R(26) TF_R(6)   x0 += ks0; x1 += ks1 + 3u;
    TF_R(17) TF_R(29) TF_R(16) TF_R(24)  x0 += ks1; x1 += ks2 + 4u;
    TF_R(13) TF_R(15) TF_R(26) TF_R(6)   x0 += ks2; x1 += ks0 + 5u;
#undef TF_R
    o0 = x0; o1 = x1;
}

// Partitionable threefry (verified R6): counter = (0, e), bits = o0 ^ o1.
__device__ __forceinline__ float jax_noise(uint32_t e) {
    uint32_t o0, o1;
    threefry_0_42(0u, e, o0, o1);
    uint32_t bits = o0 ^ o1;
    float u = __uint_as_float((bits >> 9) | 0x3f800000u) - 1.0f;
    return __fmul_rn(u, 0.01f);
}

// ---------------- K1: per-batch scalars, biasB, Wb (512 threads) -------------
__global__ __launch_bounds__(512) void k_prep(const float* __restrict__ t,
                                              const float* __restrict__ nt,
                                              const float* __restrict__ p,
                                              const float* __restrict__ wp,
                                              const float* __restrict__ bp) {
    int b = blockIdx.x, tid = threadIdx.x;
    __shared__ float snt[8];
    if (tid < 8) snt[tid] = nt[b * 8 + tid];
    __syncthreads();
    if (tid == 0) {
        float at = 0.f;
        for (int d = 0; d < 8; d++) at += snt[d] * t[b * 8 + d];
        g_at[b] = at;
        float pv = p[b];
        g_sc[b] = 1.f + 0.3f * (1.f / (1.f + expf(-pv)));
    }
    if (tid < 64) {
        float acc = 0.f;
#pragma unroll
        for (int d = 0; d < 8; d++) acc += snt[d] * bp[(10 + d) * 64 + tid];
        g_biasB[b * 64 + tid] = acc;
    }
    // Wb[b][m], m = ki*64+o, coalesced over m
    for (int m = tid; m < 6144; m += 512) {
        float a2 = 0.f;
#pragma unroll
        for (int d = 0; d < 8; d++) a2 += snt[d] * wp[(10 + d) * 6144 + m];
        g_Wb[b * 6144 + m] = a2;
    }
}

// ---------------- K2/K6: partial column sums (grid 16 x 8) -------------------
__global__ void k_colsum(const float* __restrict__ src, float* __restrict__ dst) {
    int b = blockIdx.x, g = blockIdx.y, tid = threadIdx.x;
    int c = tid & 31, r0 = tid >> 5;
    float acc = 0.f;
    int base = b * NN + g * 256;
    for (int n = r0; n < 256; n += 8) acc += src[(base + n) * 32 + c];
    __shared__ float sm[256];
    sm[tid] = acc;
    __syncthreads();
    if (tid < 32) {
        float a = sm[tid];
#pragma unroll
        for (int q = 1; q < 8; q++) a += sm[q * 32 + tid];
        dst[(b * 8 + g) * 32 + tid] = a;
    }
}

// ---------------- K3: Wn = node_emb @ wp[:10]  (skinny GEMM) -----------------
__global__ __launch_bounds__(256) void k_wn(const float* __restrict__ ne,
                                            const float* __restrict__ wp) {
    int tid = threadIdx.x;
    int col = blockIdx.y * 256 + tid;          // 0..6143
    int n0 = blockIdx.x * 16;
    __shared__ float wps[10 * 256];
    __shared__ float nes[16 * 10];
#pragma unroll
    for (int d = 0; d < 10; d++) wps[d * 256 + tid] = wp[d * 6144 + col];
    if (tid < 160) nes[tid] = ne[n0 * 10 + tid];
    __syncthreads();
    for (int nn = 0; nn < 16; nn++) {
        float acc = 0.f;
#pragma unroll
        for (int d = 0; d < 10; d++) acc += nes[nn * 10 + d] * wps[d * 256 + tid];
        g_Wn[(n0 + nn) * 6144 + col] = acc;
    }
}

// ---------------- K4: 1 row/block; warp-register top16 + single merge --------
__global__ __launch_bounds__(256) void k_select(const float* __restrict__ ne) {
    __shared__ float s_a[NN];
    __shared__ float s_wv[128];
    __shared__ int   s_wi[128];
    __shared__ float s_cv[16];
    __shared__ int   s_ci[16];

    int i = blockIdx.x, tid = threadIdx.x, lane = tid & 31, w = tid >> 5;

    float nei[10];
#pragma unroll
    for (int d = 0; d < 10; d++) nei[d] = __ldg(&ne[i * 10 + d]);

    for (int j = tid; j < NN; j += 256) {
        const float* nj = ne + j * 10;
        float acc = 0.f;
#pragma unroll
        for (int d = 0; d < 10; d++) acc += nei[d] * nj[d];
        s_a[j] = acc;
    }
    __syncthreads();

    // warp-local top-16 over its 256 values (register-resident)
    int jbase = w * 256;
    float v[8];
#pragma unroll
    for (int q = 0; q < 8; q++) v[q] = s_a[jbase + q * 32 + lane];

    for (int r = 0; r < 16; r++) {
        float bv = v[0]; int bq = 0;
#pragma unroll
        for (int q = 1; q < 8; q++) if (v[q] > bv) { bv = v[q]; bq = q; }
        int bj = jbase + bq * 32 + lane;
#pragma unroll
        for (int off = 16; off; off >>= 1) {
            float ov = __shfl_down_sync(0xffffffffu, bv, off);
            int   oj = __shfl_down_sync(0xffffffffu, bj, off);
            if (ov > bv || (ov == bv && oj < bj)) { bv = ov; bj = oj; }
        }
        bv = __shfl_sync(0xffffffffu, bv, 0);
        bj = __shfl_sync(0xffffffffu, bj, 0);
        if (lane == 0) { s_wv[w * 16 + r] = bv; s_wi[w * 16 + r] = bj; }
        if (lane == (bj & 31)) v[((bj - jbase) >> 5)] = NEGINF;
    }
    __syncthreads();

    // warp 0 merges 128 candidates -> global top-16
    if (w == 0) {
        float mv[4]; int mi[4];
#pragma unroll
        for (int q = 0; q < 4; q++) {
            mv[q] = s_wv[q * 32 + lane];
            mi[q] = s_wi[q * 32 + lane];
        }
        for (int r = 0; r < 16; r++) {
            float bv = mv[0]; int bi = mi[0];
#pragma unroll
            for (int q = 1; q < 4; q++)
                if (mv[q] > bv || (mv[q] == bv && mi[q] < bi)) { bv = mv[q]; bi = mi[q]; }
#pragma unroll
            for (int off = 16; off; off >>= 1) {
                float ov = __shfl_down_sync(0xffffffffu, bv, off);
                int   oi = __shfl_down_sync(0xffffffffu, bi, off);
                if (ov > bv || (ov == bv && oi < bi)) { bv = ov; bi = oi; }
            }
            bv = __shfl_sync(0xffffffffu, bv, 0);
            bi = __shfl_sync(0xffffffffu, bi, 0);
            if (lane == 0) { s_cv[r] = bv; s_ci[r] = bi; }
#pragma unroll
            for (int q = 0; q < 4; q++) if (mi[q] == bi) mv[q] = NEGINF;
        }
    }
    __syncthreads();

    // per-batch: warp w handles batches w and w+8
    for (int bb = 0; bb < 2; bb++) {
        int b = w + bb * 8;
        float s = g_sc[b], at = g_at[b];
        float myv = 0.f, key = NEGINF;
        int cj = -1;
        if (lane < 16) {
            cj = s_ci[lane];
            float pre = s * (s_cv[lane] + at);
            myv = pre > 0.f ? pre : 0.f;
            uint32_t e = (uint32_t)b * 4194304u + (uint32_t)i * 2048u + (uint32_t)cj;
            key = __fadd_rn(myv, jax_noise(e));
        }
        // top-10 of 16 by key
        float kwork = key;
        bool sel = false;
#pragma unroll
        for (int r = 0; r < 10; r++) {
            float bv = kwork; int bl = lane;
#pragma unroll
            for (int off = 16; off; off >>= 1) {
                float ov = __shfl_down_sync(0xffffffffu, bv, off);
                int   ol = __shfl_down_sync(0xffffffffu, bl, off);
                if (ov > bv) { bv = ov; bl = ol; }
            }
            bl = __shfl_sync(0xffffffffu, bl, 0);
            if (lane == bl) { sel = true; kwork = NEGINF; }
        }
        // softmax over 2048 entries: 10 selected values, 2038 zeros
        float mv2 = sel ? myv : NEGINF;
#pragma unroll
        for (int off = 16; off; off >>= 1)
            mv2 = fmaxf(mv2, __shfl_down_sync(0xffffffffu, mv2, off));
        float m = __shfl_sync(0xffffffffu, mv2, 0);
        float se = sel ? expf(myv - m) : 0.f;
        float ss = se;
#pragma unroll
        for (int off = 16; off; off >>= 1)
            ss += __shfl_down_sync(0xffffffffu, ss, off);
        ss = __shfl_sync(0xffffffffu, ss, 0);
        float eu = expf(-m);
        float Z = ss + 2038.f * eu;
        float unif = eu / Z;
        unsigned mask = __ballot_sync(0xffffffffu, sel);
        if (sel) {
            int pos = __popc(mask & ((1u << lane) - 1u));
            int base = (b * NN + i) * 10 + pos;
            g_sidx[base] = cj;
            g_w[base] = se / Z - unif;
        }
        if (lane == 0) g_unif[b * NN + i] = unif;
    }
}

// ---------------- K5/K7: y = A @ src (uniform + sparse); pass2: y=2y-x -------
__global__ __launch_bounds__(256) void k_spmv(const float* __restrict__ src,
                                              const float* __restrict__ cs,
                                              const float* __restrict__ x,
                                              float* __restrict__ dst, int pass2) {
    int lane = threadIdx.x & 31, w = threadIdx.x >> 5;
    int r = blockIdx.x * 8 + w;                  // r = b*2048 + n
    int b = r >> 11;
    float csv = 0.f;
#pragma unroll
    for (int g = 0; g < 8; g++) csv += cs[(b * 8 + g) * 32 + lane];
    float acc = g_unif[r] * csv;
    const int*   id = g_sidx + r * 10;
    const float* ww = g_w + r * 10;
#pragma unroll
    for (int tt = 0; tt < 10; tt++)
        acc += ww[tt] * src[(b * NN + id[tt]) * 32 + lane];
    if (pass2) acc = 2.f * acc - x[r * 32 + lane];
    dst[r * 32 + lane] = acc;
}

// ---------------- K8: per-node term + biases (writes out) --------------------
__global__ __launch_bounds__(128) void k_out1(const float* __restrict__ x,
                                              const float* __restrict__ y1,
                                              const float* __restrict__ y2,
                                              const float* __restrict__ ne,
                                              const float* __restrict__ bp,
                                              float* __restrict__ out) {
    int n = blockIdx.x, tid = threadIdx.x;
    __shared__ float sW[6144];
    __shared__ float sx[16 * 96];
    __shared__ float sbp[640];
    __shared__ float snerow[10];
    for (int m = tid; m < 6144; m += 128) sW[m] = g_Wn[n * 6144 + m];
    for (int m = tid; m < 1536; m += 128) {
        int b = m / 96, k = m - b * 96;
        const float* src = (k < 32) ? x : (k < 64) ? y1 : y2;
        sx[m] = src[(b * NN + n) * 32 + (k & 31)];
    }
    for (int m = tid; m < 640; m += 128) sbp[m] = bp[m];
    if (tid < 10) snerow[tid] = ne[n * 10 + tid];
    __syncthreads();
    int o = tid & 63, g = tid >> 6;
    float acc[8] = {0, 0, 0, 0, 0, 0, 0, 0};
    for (int k = 0; k < 96; k++) {
        float wv = sW[k * 64 + o];
#pragma unroll
        for (int q = 0; q < 8; q++) acc[q] += sx[(g + 2 * q) * 96 + k] * wv;
    }
    float bn = 0.f;
#pragma unroll
    for (int d = 0; d < 10; d++) bn += snerow[d] * sbp[d * 64 + o];
#pragma unroll
    for (int q = 0; q < 8; q++) {
        int b = g + 2 * q;
        out[((b * NN) + n) * 64 + o] = acc[q] + bn + g_biasB[b * 64 + o];
    }
}

// ---------------- K9: per-batch GEMM term, accumulates into out --------------
__global__ __launch_bounds__(256) void k_out2(const float* __restrict__ x,
                                              const float* __restrict__ y1,
                                              const float* __restrict__ y2,
                                              float* __restrict__ out) {
    int n0 = blockIdx.x * 64, b = blockIdx.y, tid = threadIdx.x;
    __shared__ float sWb[48 * 64];
    __shared__ float sxg[64 * 97];
    {
        const float* srcs[3] = {x, y1, y2};
#pragma unroll
        for (int a = 0; a < 3; a++) {
            const float* s = srcs[a];
            for (int m = tid; m < 2048; m += 256) {
                int rr = m >> 5, c = m & 31;
                sxg[rr * 97 + a * 32 + c] = s[(b * NN + n0 + rr) * 32 + c];
            }
        }
    }
    int o0 = (tid & 15) * 4, tn = tid >> 4;
    float acc[4][4];
#pragma unroll
    for (int rr = 0; rr < 4; rr++)
#pragma unroll
        for (int oo = 0; oo < 4; oo++) acc[rr][oo] = 0.f;

    for (int kc = 0; kc < 2; kc++) {
        __syncthreads();
        for (int m = tid; m < 3072; m += 256)
            sWb[m] = g_Wb[b * 6144 + kc * 3072 + m];
        __syncthreads();
        for (int k = 0; k < 48; k++) {
            float4 wv = *(const float4*)&sWb[k * 64 + o0];
#pragma unroll
            for (int rr = 0; rr < 4; rr++) {
                float xv = sxg[(tn + 16 * rr) * 97 + kc * 48 + k];
                acc[rr][0] += xv * wv.x; acc[rr][1] += xv * wv.y;
                acc[rr][2] += xv * wv.z; acc[rr][3] += xv * wv.w;
            }
        }
    }
#pragma unroll
    for (int rr = 0; rr < 4; rr++) {
        int row = tn + 16 * rr;
        float4* op = (float4*)&out[((b * NN) + (n0 + row)) * 64 + o0];
        float4 cur = *op;
        cur.x += acc[rr][0]; cur.y += acc[rr][1];
        cur.z += acc[rr][2]; cur.w += acc[rr][3];
        *op = cur;
    }
}

// ---------------- launch ------------------------------------------------------
extern "C" void kernel_launch(void* const* d_in, const int* in_sizes, int n_in,
                              void* d_out, int out_size) {
    const float* x  = (const float*)d_in[0];
    const float* ne = (const float*)d_in[1];
    const float* t  = (const float*)d_in[2];
    const float* nt = (const float*)d_in[3];
    const float* p  = (const float*)d_in[4];
    const float* wp = (const float*)d_in[5];
    const float* bp = (const float*)d_in[6];
    float* out = (float*)d_out;

    float *y1, *y2, *csx, *csy;
    cudaGetSymbolAddress((void**)&y1, g_y1);
    cudaGetSymbolAddress((void**)&y2, g_y2);
    cudaGetSymbolAddress((void**)&csx, g_csx);
    cudaGetSymbolAddress((void**)&csy, g_csy);

    k_prep<<<BSZ, 512>>>(t, nt, p, wp, bp);
    k_colsum<<<dim3(BSZ, 8), 256>>>(x, csx);
    k_wn<<<dim3(128, 24), 256>>>(ne, wp);
    k_select<<<NN, 256>>>(ne);
    k_spmv<<<4096, 256>>>(x, csx, x, y1, 0);
    k_colsum<<<dim3(BSZ, 8), 256>>>(y1, csy);
    k_spmv<<<4096, 256>>>(y1, csy, x, y2, 1);
    k_out1<<<NN, 128>>>(x, y1, y2, ne, bp, out);
    k_out2<<<dim3(32, BSZ), 256>>>(x, y1, y2, out);
}

// round 10
// speedup vs baseline: 1.7125x; 1.1005x over previous
#include <cuda_runtime.h>
#include <stdint.h>

#define NN    2048
#define BSZ   16
#define NEGINF (-1e30f)

// ---------------- device scratch (static globals; no runtime allocation) ----
static __device__ float g_at[BSZ];
static __device__ float g_sc[BSZ];
static __device__ float g_csx[BSZ * 8 * 32];   // partial colsums [b][g][c]
static __device__ float g_csy[BSZ * 8 * 32];
static __device__ float g_biasB[BSZ * 64];
static __device__ __align__(16) float g_Wb[BSZ * 96 * 64];
static __device__ __align__(16) float g_Wn[NN * 96 * 64];     // 50.3 MB
static __device__ __align__(16) float g_neT[10 * NN];         // transposed node_emb
static __device__ float g_unif[BSZ * NN];
static __device__ float g_w[BSZ * NN * 10];
static __device__ int   g_sidx[BSZ * NN * 10];
static __device__ __align__(16) float g_y1[BSZ * NN * 32];
static __device__ __align__(16) float g_y2[BSZ * NN * 32];

// ---------------- bit-exact threefry-2x32-20, key = (0, 42) -----------------
__device__ __forceinline__ void threefry_0_42(uint32_t x0, uint32_t x1,
                                              uint32_t& o0, uint32_t& o1) {
    const uint32_t ks0 = 0u, ks1 = 42u, ks2 = 0x1BD11BF0u; // 0^42^0x1BD11BDA
    x0 += ks0; x1 += ks1;
#define TF_R(r) { x0 += x1; x1 = (x1 << (r)) | (x1 >> (32 - (r))); x1 ^= x0; }
    TF_R(13) TF_R(15) TF_R(26) TF_R(6)   x0 += ks1; x1 += ks2 + 1u;
    TF_R(17) TF_R(29) TF_R(16) TF_R(24)  x0 += ks2; x1 += ks0 + 2u;
    TF_R(13) TF_R(15) TF_R(26) TF_R(6)   x0 += ks0; x1 += ks1 + 3u;
    TF_R(17) TF_R(29) TF_R(16) TF_R(24)  x0 += ks1; x1 += ks2 + 4u;
    TF_R(13) TF_R(15) TF_R(26) TF_R(6)   x0 += ks2; x1 += ks0 + 5u;
#undef TF_R
    o0 = x0; o1 = x1;
}

// Partitionable threefry (verified R6): counter = (0, e), bits = o0 ^ o1.
__device__ __forceinline__ float jax_noise(uint32_t e) {
    uint32_t o0, o1;
    threefry_0_42(0u, e, o0, o1);
    uint32_t bits = o0 ^ o1;
    float u = __uint_as_float((bits >> 9) | 0x3f800000u) - 1.0f;
    return __fmul_rn(u, 0.01f);
}

// ordered-uint transform: monotone float -> uint32
__device__ __forceinline__ uint32_t ordkey(float f) {
    uint32_t b = __float_as_uint(f);
    return (b & 0x80000000u) ? ~b : (b | 0x80000000u);
}
__device__ __forceinline__ float ordval(uint32_t u) {
    uint32_t b = (u & 0x80000000u) ? (u ^ 0x80000000u) : ~u;
    return __uint_as_float(b);
}

// ---------------- K1: per-batch scalars, biasB, Wb, neT ----------------------
__global__ __launch_bounds__(512) void k_prep(const float* __restrict__ t,
                                              const float* __restrict__ nt,
                                              const float* __restrict__ p,
                                              const float* __restrict__ wp,
                                              const float* __restrict__ bp,
                                              const float* __restrict__ ne) {
    int b = blockIdx.x, tid = threadIdx.x;
    __shared__ float snt[8];
    if (tid < 8) snt[tid] = nt[b * 8 + tid];
    __syncthreads();
    if (tid == 0) {
        float at = 0.f;
        for (int d = 0; d < 8; d++) at += snt[d] * t[b * 8 + d];
        g_at[b] = at;
        float pv = p[b];
        g_sc[b] = 1.f + 0.3f * (1.f / (1.f + expf(-pv)));
    }
    if (tid < 64) {
        float acc = 0.f;
#pragma unroll
        for (int d = 0; d < 8; d++) acc += snt[d] * bp[(10 + d) * 64 + tid];
        g_biasB[b * 64 + tid] = acc;
    }
    // transpose slice of node_emb: this block handles m in [b*1280, (b+1)*1280)
    for (int m = b * 1280 + tid; m < (b + 1) * 1280; m += 512) {
        int n = m / 10, d = m - n * 10;
        g_neT[d * NN + n] = ne[m];
    }
    // Wb[b][m], m = ki*64+o, coalesced over m
    for (int m = tid; m < 6144; m += 512) {
        float a2 = 0.f;
#pragma unroll
        for (int d = 0; d < 8; d++) a2 += snt[d] * wp[(10 + d) * 6144 + m];
        g_Wb[b * 6144 + m] = a2;
    }
}

// ---------------- K2/K6: partial column sums (grid 16 x 8) -------------------
__global__ void k_colsum(const float* __restrict__ src, float* __restrict__ dst) {
    int b = blockIdx.x, g = blockIdx.y, tid = threadIdx.x;
    int c = tid & 31, r0 = tid >> 5;
    float acc = 0.f;
    int base = b * NN + g * 256;
    for (int n = r0; n < 256; n += 8) acc += src[(base + n) * 32 + c];
    __shared__ float sm[256];
    sm[tid] = acc;
    __syncthreads();
    if (tid < 32) {
        float a = sm[tid];
#pragma unroll
        for (int q = 1; q < 8; q++) a += sm[q * 32 + tid];
        dst[(b * 8 + g) * 32 + tid] = a;
    }
}

// ---------------- K3: Wn = node_emb @ wp[:10]  (skinny GEMM) -----------------
__global__ __launch_bounds__(256) void k_wn(const float* __restrict__ ne,
                                            const float* __restrict__ wp) {
    int tid = threadIdx.x;
    int col = blockIdx.y * 256 + tid;          // 0..6143
    int n0 = blockIdx.x * 16;
    __shared__ float wps[10 * 256];
    __shared__ float nes[16 * 10];
#pragma unroll
    for (int d = 0; d < 10; d++) wps[d * 256 + tid] = wp[d * 6144 + col];
    if (tid < 160) nes[tid] = ne[n0 * 10 + tid];
    __syncthreads();
    for (int nn = 0; nn < 16; nn++) {
        float acc = 0.f;
#pragma unroll
        for (int d = 0; d < 10; d++) acc += nes[nn * 10 + d] * wps[d * 256 + tid];
        g_Wn[(n0 + nn) * 6144 + col] = acc;
    }
}

// ---------------- K4 v4: packed-key top16, coalesced dots, half-warp epilogue
__global__ __launch_bounds__(256) void k_select(const float* __restrict__ ne) {
    __shared__ uint64_t s_wk[128];   // per-warp candidates (packed)
    __shared__ uint64_t s_ck[16];    // merged top-16 (packed, desc)

    int i = blockIdx.x, tid = threadIdx.x, lane = tid & 31, w = tid >> 5;

    float nei[10];
#pragma unroll
    for (int d = 0; d < 10; d++) nei[d] = __ldg(&ne[i * 10 + d]);

    // dots: lane-major mapping j = w*256 + lane*8 + q ; float4 coalesced loads
    int jbase = w * 256 + lane * 8;
    float acc[8] = {0, 0, 0, 0, 0, 0, 0, 0};
#pragma unroll
    for (int d = 0; d < 10; d++) {
        const float4* rp = (const float4*)&g_neT[d * NN + jbase];
        float4 a0 = rp[0], a1 = rp[1];
        float c = nei[d];
        acc[0] += c * a0.x; acc[1] += c * a0.y; acc[2] += c * a0.z; acc[3] += c * a0.w;
        acc[4] += c * a1.x; acc[5] += c * a1.y; acc[6] += c * a1.z; acc[7] += c * a1.w;
    }
    uint64_t k[8];
#pragma unroll
    for (int q = 0; q < 8; q++)
        k[q] = ((uint64_t)ordkey(acc[q]) << 32) | (uint32_t)(2047 - (jbase + q));

    // warp-local top-16 (packed keys: value desc, index asc on ties)
    for (int r = 0; r < 16; r++) {
        uint64_t bk = k[0];
#pragma unroll
        for (int q = 1; q < 8; q++) if (k[q] > bk) bk = k[q];
#pragma unroll
        for (int off = 16; off; off >>= 1) {
            uint64_t ok = __shfl_down_sync(0xffffffffu, bk, off);
            if (ok > bk) bk = ok;
        }
        bk = __shfl_sync(0xffffffffu, bk, 0);
        if (lane == 0) s_wk[w * 16 + r] = bk;
        int bj = 2047 - (int)(bk & 0x7ffu);
        if (lane == ((bj - w * 256) >> 3)) {
            int q = bj & 7;
#pragma unroll
            for (int qq = 0; qq < 8; qq++) if (qq == q) k[qq] = 0ull;
        }
    }
    __syncthreads();

    // warp 0 merges 128 candidates -> global top-16 (desc)
    if (w == 0) {
        uint64_t mk[4];
#pragma unroll
        for (int q = 0; q < 4; q++) mk[q] = s_wk[q * 32 + lane];
        for (int r = 0; r < 16; r++) {
            uint64_t bk = mk[0];
#pragma unroll
            for (int q = 1; q < 4; q++) if (mk[q] > bk) bk = mk[q];
#pragma unroll
            for (int off = 16; off; off >>= 1) {
                uint64_t ok = __shfl_down_sync(0xffffffffu, bk, off);
                if (ok > bk) bk = ok;
            }
            bk = __shfl_sync(0xffffffffu, bk, 0);
            if (lane == 0) s_ck[r] = bk;
#pragma unroll
            for (int q = 0; q < 4; q++) if (mk[q] == bk) mk[q] = 0ull;
        }
    }
    __syncthreads();

    // epilogue: half-warp per batch (lanes 0-15 -> b=w, 16-31 -> b=w+8)
    {
        int L = lane & 15;
        int b = w + ((lane & 16) ? 8 : 0);
        uint64_t ck = s_ck[L];
        int   cj = 2047 - (int)(ck & 0x7ffu);
        float cv = ordval((uint32_t)(ck >> 32));

        float s = g_sc[b], at = g_at[b];
        float pre = s * (cv + at);
        float myv = pre > 0.f ? pre : 0.f;
        uint32_t e = (uint32_t)b * 4194304u + (uint32_t)i * 2048u + (uint32_t)cj;
        float key = __fadd_rn(myv, jax_noise(e));

        // rank within half-warp: selected iff rank < 10
        int half = lane & 16;
        int rank = 0;
#pragma unroll
        for (int kk = 0; kk < 16; kk++) {
            float ok = __shfl_sync(0xffffffffu, key, half + kk);
            rank += (ok > key) || (ok == key && kk < L);
        }
        bool sel = rank < 10;

        // softmax over 2048: 10 selected values, 2038 zeros
        float mv = sel ? myv : NEGINF;
#pragma unroll
        for (int off = 8; off; off >>= 1)
            mv = fmaxf(mv, __shfl_xor_sync(0xffffffffu, mv, off));
        float se = sel ? expf(myv - mv) : 0.f;
        float ss = se;
#pragma unroll
        for (int off = 8; off; off >>= 1)
            ss += __shfl_xor_sync(0xffffffffu, ss, off);
        float eu = expf(-mv);
        float Z = ss + 2038.f * eu;
        float unif = eu / Z;

        unsigned mask = __ballot_sync(0xffffffffu, sel);
        unsigned hm = half ? (mask >> 16) : (mask & 0xffffu);
        if (sel) {
            int pos = __popc(hm & ((1u << L) - 1u));
            int base = (b * NN + i) * 10 + pos;
            g_sidx[base] = cj;
            g_w[base] = se / Z - unif;
        }
        if (L == 0) g_unif[b * NN + i] = unif;
    }
}

// ---------------- K5/K7: y = A @ src (uniform + sparse); pass2: y=2y-x -------
__global__ __launch_bounds__(256) void k_spmv(const float* __restrict__ src,
                                              const float* __restrict__ cs,
                                              const float* __restrict__ x,
                                              float* __restrict__ dst, int pass2) {
    int lane = threadIdx.x & 31, w = threadIdx.x >> 5;
    int r = blockIdx.x * 8 + w;                  // r = b*2048 + n
    int b = r >> 11;
    float csv = 0.f;
#pragma unroll
    for (int g = 0; g < 8; g++) csv += cs[(b * 8 + g) * 32 + lane];
    float acc = g_unif[r] * csv;
    const int*   id = g_sidx + r * 10;
    const float* ww = g_w + r * 10;
#pragma unroll
    for (int tt = 0; tt < 10; tt++)
        acc += ww[tt] * src[(b * NN + id[tt]) * 32 + lane];
    if (pass2) acc = 2.f * acc - x[r * 32 + lane];
    dst[r * 32 + lane] = acc;
}

// ---------------- K8: per-node term + biases (writes out) --------------------
__global__ __launch_bounds__(128) void k_out1(const float* __restrict__ x,
                                              const float* __restrict__ y1,
                                              const float* __restrict__ y2,
                                              const float* __restrict__ ne,
                                              const float* __restrict__ bp,
                                              float* __restrict__ out) {
    int n = blockIdx.x, tid = threadIdx.x;
    __shared__ float sW[6144];
    __shared__ float sx[16 * 96];
    __shared__ float sbp[640];
    __shared__ float snerow[10];
    for (int m = tid; m < 6144; m += 128) sW[m] = g_Wn[n * 6144 + m];
    for (int m = tid; m < 1536; m += 128) {
        int b = m / 96, k = m - b * 96;
        const float* src = (k < 32) ? x : (k < 64) ? y1 : y2;
        sx[m] = src[(b * NN + n) * 32 + (k & 31)];
    }
    for (int m = tid; m < 640; m += 128) sbp[m] = bp[m];
    if (tid < 10) snerow[tid] = ne[n * 10 + tid];
    __syncthreads();
    int o = tid & 63, g = tid >> 6;
    float acc[8] = {0, 0, 0, 0, 0, 0, 0, 0};
    for (int k = 0; k < 96; k++) {
        float wv = sW[k * 64 + o];
#pragma unroll
        for (int q = 0; q < 8; q++) acc[q] += sx[(g + 2 * q) * 96 + k] * wv;
    }
    float bn = 0.f;
#pragma unroll
    for (int d = 0; d < 10; d++) bn += snerow[d] * sbp[d * 64 + o];
#pragma unroll
    for (int q = 0; q < 8; q++) {
        int b = g + 2 * q;
        out[((b * NN) + n) * 64 + o] = acc[q] + bn + g_biasB[b * 64 + o];
    }
}

// ---------------- K9: per-batch GEMM term, accumulates into out --------------
__global__ __launch_bounds__(256) void k_out2(const float* __restrict__ x,
                                              const float* __restrict__ y1,
                                              const float* __restrict__ y2,
                                              float* __restrict__ out) {
    int n0 = blockIdx.x * 64, b = blockIdx.y, tid = threadIdx.x;
    __shared__ float sWb[48 * 64];
    __shared__ float sxg[64 * 97];
    {
        const float* srcs[3] = {x, y1, y2};
#pragma unroll
        for (int a = 0; a < 3; a++) {
            const float* s = srcs[a];
            for (int m = tid; m < 2048; m += 256) {
                int rr = m >> 5, c = m & 31;
                sxg[rr * 97 + a * 32 + c] = s[(b * NN + n0 + rr) * 32 + c];
            }
        }
    }
    int o0 = (tid & 15) * 4, tn = tid >> 4;
    float acc[4][4];
#pragma unroll
    for (int rr = 0; rr < 4; rr++)
#pragma unroll
        for (int oo = 0; oo < 4; oo++) acc[rr][oo] = 0.f;

    for (int kc = 0; kc < 2; kc++) {
        __syncthreads();
        for (int m = tid; m < 3072; m += 256)
            sWb[m] = g_Wb[b * 6144 + kc * 3072 + m];
        __syncthreads();
        for (int k = 0; k < 48; k++) {
            float4 wv = *(const float4*)&sWb[k * 64 + o0];
#pragma unroll
            for (int rr = 0; rr < 4; rr++) {
                float xv = sxg[(tn + 16 * rr) * 97 + kc * 48 + k];
                acc[rr][0] += xv * wv.x; acc[rr][1] += xv * wv.y;
                acc[rr][2] += xv * wv.z; acc[rr][3] += xv * wv.w;
            }
        }
    }
#pragma unroll
    for (int rr = 0; rr < 4; rr++) {
        int row = tn + 16 * rr;
        float4* op = (float4*)&out[((b * NN) + (n0 + row)) * 64 + o0];
        float4 cur = *op;
        cur.x += acc[rr][0]; cur.y += acc[rr][1];
        cur.z += acc[rr][2]; cur.w += acc[rr][3];
        *op = cur;
    }
}

// ---------------- launch ------------------------------------------------------
extern "C" void kernel_launch(void* const* d_in, const int* in_sizes, int n_in,
                              void* d_out, int out_size) {
    const float* x  = (const float*)d_in[0];
    const float* ne = (const float*)d_in[1];
    const float* t  = (const float*)d_in[2];
    const float* nt = (const float*)d_in[3];
    const float* p  = (const float*)d_in[4];
    const float* wp = (const float*)d_in[5];
    const float* bp = (const float*)d_in[6];
    float* out = (float*)d_out;

    float *y1, *y2, *csx, *csy;
    cudaGetSymbolAddress((void**)&y1, g_y1);
    cudaGetSymbolAddress((void**)&y2, g_y2);
    cudaGetSymbolAddress((void**)&csx, g_csx);
    cudaGetSymbolAddress((void**)&csy, g_csy);

    k_prep<<<BSZ, 512>>>(t, nt, p, wp, bp, ne);
    k_colsum<<<dim3(BSZ, 8), 256>>>(x, csx);
    k_wn<<<dim3(128, 24), 256>>>(ne, wp);
    k_select<<<NN, 256>>>(ne);
    k_spmv<<<4096, 256>>>(x, csx, x, y1, 0);
    k_colsum<<<dim3(BSZ, 8), 256>>>(y1, csy);
    k_spmv<<<4096, 256>>>(y1, csy, x, y2, 1);
    k_out1<<<NN, 128>>>(x, y1, y2, ne, bp, out);
    k_out2<<<dim3(32, BSZ), 256>>>(x, y1, y2, out);
}

// round 11
// speedup vs baseline: 2.0422x; 1.1925x over previous
#include <cuda_runtime.h>
#include <stdint.h>

#define NN    2048
#define BSZ   16
#define NEGINF (-1e30f)

// ---------------- device scratch (static globals; no runtime allocation) ----
static __device__ float g_at[BSZ];
static __device__ float g_sc[BSZ];
static __device__ float g_csx[BSZ * 8 * 32];   // partial colsums [b][g][c]
static __device__ float g_csy[BSZ * 8 * 32];
static __device__ float g_biasB[BSZ * 64];
static __device__ __align__(16) float g_Wb[BSZ * 96 * 64];
static __device__ __align__(16) float g_Wn[NN * 96 * 64];     // 50.3 MB
static __device__ __align__(16) float g_neT[10 * NN];         // transposed node_emb
static __device__ float g_unif[BSZ * NN];
static __device__ float g_w[BSZ * NN * 10];
static __device__ int   g_sidx[BSZ * NN * 10];
static __device__ __align__(16) float g_y1[BSZ * NN * 32];
static __device__ __align__(16) float g_y2[BSZ * NN * 32];

// ---------------- bit-exact threefry-2x32-20, key = (0, 42) -----------------
__device__ __forceinline__ void threefry_0_42(uint32_t x0, uint32_t x1,
                                              uint32_t& o0, uint32_t& o1) {
    const uint32_t ks0 = 0u, ks1 = 42u, ks2 = 0x1BD11BF0u; // 0^42^0x1BD11BDA
    x0 += ks0; x1 += ks1;
#define TF_R(r) { x0 += x1; x1 = (x1 << (r)) | (x1 >> (32 - (r))); x1 ^= x0; }
    TF_R(13) TF_R(15) TF_R(26) TF_R(6)   x0 += ks1; x1 += ks2 + 1u;
    TF_R(17) TF_R(29) TF_R(16) TF_R(24)  x0 += ks2; x1 += ks0 + 2u;
    TF_R(13) TF_R(15) TF_R(26) TF_R(6)   x0 += ks0; x1 += ks1 + 3u;
    TF_R(17) TF_R(29) TF_R(16) TF_R(24)  x0 += ks1; x1 += ks2 + 4u;
    TF_R(13) TF_R(15) TF_R(26) TF_R(6)   x0 += ks2; x1 += ks0 + 5u;
#undef TF_R
    o0 = x0; o1 = x1;
}

// Partitionable threefry (verified R6): counter = (0, e), bits = o0 ^ o1.
__device__ __forceinline__ float jax_noise(uint32_t e) {
    uint32_t o0, o1;
    threefry_0_42(0u, e, o0, o1);
    uint32_t bits = o0 ^ o1;
    float u = __uint_as_float((bits >> 9) | 0x3f800000u) - 1.0f;
    return __fmul_rn(u, 0.01f);
}

// ordered-uint transform: monotone float -> uint32
__device__ __forceinline__ uint32_t ordkey(float f) {
    uint32_t b = __float_as_uint(f);
    return (b & 0x80000000u) ? ~b : (b | 0x80000000u);
}
__device__ __forceinline__ float ordval(uint32_t u) {
    uint32_t b = (u & 0x80000000u) ? (u ^ 0x80000000u) : ~u;
    return __uint_as_float(b);
}

// ---------------- K1: per-batch scalars, biasB, Wb, neT ----------------------
__global__ __launch_bounds__(512) void k_prep(const float* __restrict__ t,
                                              const float* __restrict__ nt,
                                              const float* __restrict__ p,
                                              const float* __restrict__ wp,
                                              const float* __restrict__ bp,
                                              const float* __restrict__ ne) {
    int b = blockIdx.x, tid = threadIdx.x;
    __shared__ float snt[8];
    if (tid < 8) snt[tid] = nt[b * 8 + tid];
    __syncthreads();
    if (tid == 0) {
        float at = 0.f;
        for (int d = 0; d < 8; d++) at += snt[d] * t[b * 8 + d];
        g_at[b] = at;
        float pv = p[b];
        g_sc[b] = 1.f + 0.3f * (1.f / (1.f + expf(-pv)));
    }
    if (tid < 64) {
        float acc = 0.f;
#pragma unroll
        for (int d = 0; d < 8; d++) acc += snt[d] * bp[(10 + d) * 64 + tid];
        g_biasB[b * 64 + tid] = acc;
    }
    // transpose slice of node_emb: this block handles m in [b*1280, (b+1)*1280)
    for (int m = b * 1280 + tid; m < (b + 1) * 1280; m += 512) {
        int n = m / 10, d = m - n * 10;
        g_neT[d * NN + n] = ne[m];
    }
    // Wb[b][m], m = ki*64+o, coalesced over m
    for (int m = tid; m < 6144; m += 512) {
        float a2 = 0.f;
#pragma unroll
        for (int d = 0; d < 8; d++) a2 += snt[d] * wp[(10 + d) * 6144 + m];
        g_Wb[b * 6144 + m] = a2;
    }
}

// ---------------- K2/K6: partial column sums (grid 16 x 8) -------------------
__global__ void k_colsum(const float* __restrict__ src, float* __restrict__ dst) {
    int b = blockIdx.x, g = blockIdx.y, tid = threadIdx.x;
    int c = tid & 31, r0 = tid >> 5;
    float acc = 0.f;
    int base = b * NN + g * 256;
    for (int n = r0; n < 256; n += 8) acc += src[(base + n) * 32 + c];
    __shared__ float sm[256];
    sm[tid] = acc;
    __syncthreads();
    if (tid < 32) {
        float a = sm[tid];
#pragma unroll
        for (int q = 1; q < 8; q++) a += sm[q * 32 + tid];
        dst[(b * 8 + g) * 32 + tid] = a;
    }
}

// ---------------- K3: Wn = node_emb @ wp[:10]  (skinny GEMM) -----------------
__global__ __launch_bounds__(256) void k_wn(const float* __restrict__ ne,
                                            const float* __restrict__ wp) {
    int tid = threadIdx.x;
    int col = blockIdx.y * 256 + tid;          // 0..6143
    int n0 = blockIdx.x * 16;
    __shared__ float wps[10 * 256];
    __shared__ float nes[16 * 10];
#pragma unroll
    for (int d = 0; d < 10; d++) wps[d * 256 + tid] = wp[d * 6144 + col];
    if (tid < 160) nes[tid] = ne[n0 * 10 + tid];
    __syncthreads();
    for (int nn = 0; nn < 16; nn++) {
        float acc = 0.f;
#pragma unroll
        for (int d = 0; d < 10; d++) acc += nes[nn * 10 + d] * wps[d * 256 + tid];
        g_Wn[(n0 + nn) * 6144 + col] = acc;
    }
}

// ---------------- K4 v5: REDUX selection rounds ------------------------------
#define CE(a, b) { if (v[a] < v[b]) { uint64_t _t = v[a]; v[a] = v[b]; v[b] = _t; } }

__global__ __launch_bounds__(256) void k_select(const float* __restrict__ ne) {
    __shared__ uint64_t s_wk[128];   // per-warp candidates (packed)
    __shared__ uint64_t s_ck[16];    // merged top-16 (packed, desc)

    int i = blockIdx.x, tid = threadIdx.x, lane = tid & 31, w = tid >> 5;

    float nei[10];
#pragma unroll
    for (int d = 0; d < 10; d++) nei[d] = __ldg(&ne[i * 10 + d]);

    // dots: lane-major mapping j = w*256 + lane*8 + q ; float4 coalesced loads
    int jbase = w * 256 + lane * 8;
    float acc[8] = {0, 0, 0, 0, 0, 0, 0, 0};
#pragma unroll
    for (int d = 0; d < 10; d++) {
        const float4* rp = (const float4*)&g_neT[d * NN + jbase];
        float4 a0 = rp[0], a1 = rp[1];
        float c = nei[d];
        acc[0] += c * a0.x; acc[1] += c * a0.y; acc[2] += c * a0.z; acc[3] += c * a0.w;
        acc[4] += c * a1.x; acc[5] += c * a1.y; acc[6] += c * a1.z; acc[7] += c * a1.w;
    }
    uint64_t v[8];
#pragma unroll
    for (int q = 0; q < 8; q++)
        v[q] = ((uint64_t)ordkey(acc[q]) << 32) | (uint32_t)(2047 - (jbase + q));

    // sort lane's 8 keys desc (Batcher 19-CE network); idx asc at value ties
    CE(0,1) CE(2,3) CE(4,5) CE(6,7)
    CE(0,2) CE(1,3) CE(4,6) CE(5,7)
    CE(1,2) CE(5,6) CE(0,4) CE(3,7)
    CE(1,5) CE(2,6)
    CE(1,4) CE(3,6)
    CE(2,4) CE(3,5)
    CE(3,4)

    // 16 REDUX rounds: warp-local top-16 (value desc, idx asc)
    for (int r = 0; r < 16; r++) {
        uint32_t hi = (uint32_t)(v[0] >> 32);
        uint32_t mx = __reduce_max_sync(0xffffffffu, hi);
        uint32_t lo = (hi == mx) ? (uint32_t)v[0] : 0u;
        uint32_t mlo = __reduce_max_sync(0xffffffffu, lo);   // max (2047-j) = min j
        if (lane == 0) s_wk[w * 16 + r] = ((uint64_t)mx << 32) | mlo;
        if (hi == mx && (uint32_t)v[0] == mlo) {             // unique winner
            v[0] = v[1]; v[1] = v[2]; v[2] = v[3]; v[3] = v[4];
            v[4] = v[5]; v[5] = v[6]; v[6] = v[7]; v[7] = 0ull;
        }
    }
    __syncthreads();

    // warp 0 merges 128 candidates -> global top-16 (desc)
    if (w == 0) {
        uint64_t v[4];
#pragma unroll
        for (int q = 0; q < 4; q++) v[q] = s_wk[q * 32 + lane];
        CE(0,1) CE(2,3) CE(0,2) CE(1,3) CE(1,2)              // sort-4 desc
        for (int r = 0; r < 16; r++) {
            uint32_t hi = (uint32_t)(v[0] >> 32);
            uint32_t mx = __reduce_max_sync(0xffffffffu, hi);
            uint32_t lo = (hi == mx) ? (uint32_t)v[0] : 0u;
            uint32_t mlo = __reduce_max_sync(0xffffffffu, lo);
            if (lane == 0) s_ck[r] = ((uint64_t)mx << 32) | mlo;
            if (hi == mx && (uint32_t)v[0] == mlo) {
                v[0] = v[1]; v[1] = v[2]; v[2] = v[3]; v[3] = 0ull;
            }
        }
    }
    __syncthreads();

    // epilogue: half-warp per batch (lanes 0-15 -> b=w, 16-31 -> b=w+8)
    {
        int L = lane & 15;
        int b = w + ((lane & 16) ? 8 : 0);
        uint64_t ck = s_ck[L];
        int   cj = 2047 - (int)(ck & 0x7ffu);
        float cv = ordval((uint32_t)(ck >> 32));

        float s = g_sc[b], at = g_at[b];
        float pre = s * (cv + at);
        float myv = pre > 0.f ? pre : 0.f;
        uint32_t e = (uint32_t)b * 4194304u + (uint32_t)i * 2048u + (uint32_t)cj;
        float key = __fadd_rn(myv, jax_noise(e));

        // rank within half-warp: selected iff rank < 10
        int half = lane & 16;
        int rank = 0;
#pragma unroll
        for (int kk = 0; kk < 16; kk++) {
            float ok = __shfl_sync(0xffffffffu, key, half + kk);
            rank += (ok > key) || (ok == key && kk < L);
        }
        bool sel = rank < 10;

        // softmax over 2048: 10 selected values, 2038 zeros
        float mv = sel ? myv : NEGINF;
#pragma unroll
        for (int off = 8; off; off >>= 1)
            mv = fmaxf(mv, __shfl_xor_sync(0xffffffffu, mv, off));
        float se = sel ? expf(myv - mv) : 0.f;
        float ss = se;
#pragma unroll
        for (int off = 8; off; off >>= 1)
            ss += __shfl_xor_sync(0xffffffffu, ss, off);
        float eu = expf(-mv);
        float Z = ss + 2038.f * eu;
        float unif = eu / Z;

        unsigned mask = __ballot_sync(0xffffffffu, sel);
        unsigned hm = half ? (mask >> 16) : (mask & 0xffffu);
        if (sel) {
            int pos = __popc(hm & ((1u << L) - 1u));
            int base = (b * NN + i) * 10 + pos;
            g_sidx[base] = cj;
            g_w[base] = se / Z - unif;
        }
        if (L == 0) g_unif[b * NN + i] = unif;
    }
}
#undef CE

// ---------------- K5/K7: y = A @ src (uniform + sparse); pass2: y=2y-x -------
__global__ __launch_bounds__(256) void k_spmv(const float* __restrict__ src,
                                              const float* __restrict__ cs,
                                              const float* __restrict__ x,
                                              float* __restrict__ dst, int pass2) {
    int lane = threadIdx.x & 31, w = threadIdx.x >> 5;
    int r = blockIdx.x * 8 + w;                  // r = b*2048 + n
    int b = r >> 11;
    float csv = 0.f;
#pragma unroll
    for (int g = 0; g < 8; g++) csv += cs[(b * 8 + g) * 32 + lane];
    float acc = g_unif[r] * csv;
    const int*   id = g_sidx + r * 10;
    const float* ww = g_w + r * 10;
#pragma unroll
    for (int tt = 0; tt < 10; tt++)
        acc += ww[tt] * src[(b * NN + id[tt]) * 32 + lane];
    if (pass2) acc = 2.f * acc - x[r * 32 + lane];
    dst[r * 32 + lane] = acc;
}

// ---------------- K8: per-node term + biases (writes out) --------------------
__global__ __launch_bounds__(128) void k_out1(const float* __restrict__ x,
                                              const float* __restrict__ y1,
                                              const float* __restrict__ y2,
                                              const float* __restrict__ ne,
                                              const float* __restrict__ bp,
                                              float* __restrict__ out) {
    int n = blockIdx.x, tid = threadIdx.x;
    __shared__ float sW[6144];
    __shared__ float sx[16 * 96];
    __shared__ float sbp[640];
    __shared__ float snerow[10];
    for (int m = tid; m < 6144; m += 128) sW[m] = g_Wn[n * 6144 + m];
    for (int m = tid; m < 1536; m += 128) {
        int b = m / 96, k = m - b * 96;
        const float* src = (k < 32) ? x : (k < 64) ? y1 : y2;
        sx[m] = src[(b * NN + n) * 32 + (k & 31)];
    }
    for (int m = tid; m < 640; m += 128) sbp[m] = bp[m];
    if (tid < 10) snerow[tid] = ne[n * 10 + tid];
    __syncthreads();
    int o = tid & 63, g = tid >> 6;
    float acc[8] = {0, 0, 0, 0, 0, 0, 0, 0};
    for (int k = 0; k < 96; k++) {
        float wv = sW[k * 64 + o];
#pragma unroll
        for (int q = 0; q < 8; q++) acc[q] += sx[(g + 2 * q) * 96 + k] * wv;
    }
    float bn = 0.f;
#pragma unroll
    for (int d = 0; d < 10; d++) bn += snerow[d] * sbp[d * 64 + o];
#pragma unroll
    for (int q = 0; q < 8; q++) {
        int b = g + 2 * q;
        out[((b * NN) + n) * 64 + o] = acc[q] + bn + g_biasB[b * 64 + o];
    }
}

// ---------------- K9: per-batch GEMM term, accumulates into out --------------
__global__ __launch_bounds__(256) void k_out2(const float* __restrict__ x,
                                              const float* __restrict__ y1,
                                              const float* __restrict__ y2,
                                              float* __restrict__ out) {
    int n0 = blockIdx.x * 64, b = blockIdx.y, tid = threadIdx.x;
    __shared__ float sWb[48 * 64];
    __shared__ float sxg[64 * 97];
    {
        const float* srcs[3] = {x, y1, y2};
#pragma unroll
        for (int a = 0; a < 3; a++) {
            const float* s = srcs[a];
            for (int m = tid; m < 2048; m += 256) {
                int rr = m >> 5, c = m & 31;
                sxg[rr * 97 + a * 32 + c] = s[(b * NN + n0 + rr) * 32 + c];
            }
        }
    }
    int o0 = (tid & 15) * 4, tn = tid >> 4;
    float acc[4][4];
#pragma unroll
    for (int rr = 0; rr < 4; rr++)
#pragma unroll
        for (int oo = 0; oo < 4; oo++) acc[rr][oo] = 0.f;

    for (int kc = 0; kc < 2; kc++) {
        __syncthreads();
        for (int m = tid; m < 3072; m += 256)
            sWb[m] = g_Wb[b * 6144 + kc * 3072 + m];
        __syncthreads();
        for (int k = 0; k < 48; k++) {
            float4 wv = *(const float4*)&sWb[k * 64 + o0];
#pragma unroll
            for (int rr = 0; rr < 4; rr++) {
                float xv = sxg[(tn + 16 * rr) * 97 + kc * 48 + k];
                acc[rr][0] += xv * wv.x; acc[rr][1] += xv * wv.y;
                acc[rr][2] += xv * wv.z; acc[rr][3] += xv * wv.w;
            }
        }
    }
#pragma unroll
    for (int rr = 0; rr < 4; rr++) {
        int row = tn + 16 * rr;
        float4* op = (float4*)&out[((b * NN) + (n0 + row)) * 64 + o0];
        float4 cur = *op;
        cur.x += acc[rr][0]; cur.y += acc[rr][1];
        cur.z += acc[rr][2]; cur.w += acc[rr][3];
        *op = cur;
    }
}

// ---------------- launch ------------------------------------------------------
extern "C" void kernel_launch(void* const* d_in, const int* in_sizes, int n_in,
                              void* d_out, int out_size) {
    const float* x  = (const float*)d_in[0];
    const float* ne = (const float*)d_in[1];
    const float* t  = (const float*)d_in[2];
    const float* nt = (const float*)d_in[3];
    const float* p  = (const float*)d_in[4];
    const float* wp = (const float*)d_in[5];
    const float* bp = (const float*)d_in[6];
    float* out = (float*)d_out;

    float *y1, *y2, *csx, *csy;
    cudaGetSymbolAddress((void**)&y1, g_y1);
    cudaGetSymbolAddress((void**)&y2, g_y2);
    cudaGetSymbolAddress((void**)&csx, g_csx);
    cudaGetSymbolAddress((void**)&csy, g_csy);

    k_prep<<<BSZ, 512>>>(t, nt, p, wp, bp, ne);
    k_colsum<<<dim3(BSZ, 8), 256>>>(x, csx);
    k_wn<<<dim3(128, 24), 256>>>(ne, wp);
    k_select<<<NN, 256>>>(ne);
    k_spmv<<<4096, 256>>>(x, csx, x, y1, 0);
    k_colsum<<<dim3(BSZ, 8), 256>>>(y1, csy);
    k_spmv<<<4096, 256>>>(y1, csy, x, y2, 1);
    k_out1<<<NN, 128>>>(x, y1, y2, ne, bp, out);
    k_out2<<<dim3(32, BSZ), 256>>>(x, y1, y2, out);
}

// round 12
// speedup vs baseline: 2.0804x; 1.0187x over previous
#include <cuda_runtime.h>
#include <cuda_fp16.h>
#include <stdint.h>

#define NN    2048
#define BSZ   16
#define NEGINF (-1e30f)

// ---------------- device scratch (static globals; no runtime allocation) ----
static __device__ float g_at[BSZ];
static __device__ float g_sc[BSZ];
static __device__ float g_csx[BSZ * 8 * 32];    // partial colsums of x [b][g][c]
static __device__ float g_csy2[BSZ * 32 * 32];  // partial colsums of y1 [b][slot][c]
static __device__ float g_biasB[BSZ * 64];
static __device__ __align__(16) float  g_Wb[BSZ * 96 * 64];
static __device__ __align__(16) __half g_WnH[NN * 96 * 64];   // 25 MB (fp16)
static __device__ __align__(16) float  g_neT[10 * NN];        // transposed node_emb
static __device__ float g_unif[BSZ * NN];
static __device__ float g_w[BSZ * NN * 10];
static __device__ int   g_sidx[BSZ * NN * 10];
static __device__ __align__(16) float g_y1[BSZ * NN * 32];
static __device__ __align__(16) float g_y2[BSZ * NN * 32];

// ---------------- bit-exact threefry-2x32-20, key = (0, 42) -----------------
__device__ __forceinline__ void threefry_0_42(uint32_t x0, uint32_t x1,
                                              uint32_t& o0, uint32_t& o1) {
    const uint32_t ks0 = 0u, ks1 = 42u, ks2 = 0x1BD11BF0u; // 0^42^0x1BD11BDA
    x0 += ks0; x1 += ks1;
#define TF_R(r) { x0 += x1; x1 = (x1 << (r)) | (x1 >> (32 - (r))); x1 ^= x0; }
    TF_R(13) TF_R(15) TF_R(26) TF_R(6)   x0 += ks1; x1 += ks2 + 1u;
    TF_R(17) TF_R(29) TF_R(16) TF_R(24)  x0 += ks2; x1 += ks0 + 2u;
    TF_R(13) TF_R(15) TF_R(26) TF_R(6)   x0 += ks0; x1 += ks1 + 3u;
    TF_R(17) TF_R(29) TF_R(16) TF_R(24)  x0 += ks1; x1 += ks2 + 4u;
    TF_R(13) TF_R(15) TF_R(26) TF_R(6)   x0 += ks2; x1 += ks0 + 5u;
#undef TF_R
    o0 = x0; o1 = x1;
}

// Partitionable threefry (verified R6): counter = (0, e), bits = o0 ^ o1.
__device__ __forceinline__ float jax_noise(uint32_t e) {
    uint32_t o0, o1;
    threefry_0_42(0u, e, o0, o1);
    uint32_t bits = o0 ^ o1;
    float u = __uint_as_float((bits >> 9) | 0x3f800000u) - 1.0f;
    return __fmul_rn(u, 0.01f);
}

// ordered-uint transform: monotone float -> uint32
__device__ __forceinline__ uint32_t ordkey(float f) {
    uint32_t b = __float_as_uint(f);
    return (b & 0x80000000u) ? ~b : (b | 0x80000000u);
}
__device__ __forceinline__ float ordval(uint32_t u) {
    uint32_t b = (u & 0x80000000u) ? (u ^ 0x80000000u) : ~u;
    return __uint_as_float(b);
}

// ---------------- K1: prep (role 0) + colsum_x (roles 1..8) ------------------
__global__ __launch_bounds__(512) void k_prep(const float* __restrict__ t,
                                              const float* __restrict__ nt,
                                              const float* __restrict__ p,
                                              const float* __restrict__ wp,
                                              const float* __restrict__ bp,
                                              const float* __restrict__ ne,
                                              const float* __restrict__ x) {
    int b = blockIdx.x, role = blockIdx.y, tid = threadIdx.x;
    if (role == 0) {
        __shared__ float snt[8];
        if (tid < 8) snt[tid] = nt[b * 8 + tid];
        __syncthreads();
        if (tid == 0) {
            float at = 0.f;
            for (int d = 0; d < 8; d++) at += snt[d] * t[b * 8 + d];
            g_at[b] = at;
            float pv = p[b];
            g_sc[b] = 1.f + 0.3f * (1.f / (1.f + expf(-pv)));
        }
        if (tid < 64) {
            float acc = 0.f;
#pragma unroll
            for (int d = 0; d < 8; d++) acc += snt[d] * bp[(10 + d) * 64 + tid];
            g_biasB[b * 64 + tid] = acc;
        }
        // zero csy2 partials for this batch
        for (int m = tid; m < 1024; m += 512) g_csy2[b * 1024 + m] = 0.f;
        // transpose slice of node_emb
        for (int m = b * 1280 + tid; m < (b + 1) * 1280; m += 512) {
            int n = m / 10, d = m - n * 10;
            g_neT[d * NN + n] = ne[m];
        }
        // Wb
        for (int m = tid; m < 6144; m += 512) {
            float a2 = 0.f;
#pragma unroll
            for (int d = 0; d < 8; d++) a2 += snt[d] * wp[(10 + d) * 6144 + m];
            g_Wb[b * 6144 + m] = a2;
        }
    } else {
        int g = role - 1;
        int c = tid & 31, r0 = tid >> 5;
        float acc = 0.f;
        int base = b * NN + g * 256;
        for (int n = r0; n < 256; n += 16) acc += x[(base + n) * 32 + c];
        __shared__ float sm[512];
        sm[tid] = acc;
        __syncthreads();
        if (tid < 32) {
            float a = sm[tid];
#pragma unroll
            for (int q = 1; q < 16; q++) a += sm[q * 32 + tid];
            g_csx[(b * 8 + g) * 32 + tid] = a;
        }
    }
}

// ---------------- K3: Wn = node_emb @ wp[:10], stored fp16 -------------------
__global__ __launch_bounds__(256) void k_wn(const float* __restrict__ ne,
                                            const float* __restrict__ wp) {
    int tid = threadIdx.x;
    int col = blockIdx.y * 256 + tid;          // 0..6143
    int n0 = blockIdx.x * 16;
    __shared__ float wps[10 * 256];
    __shared__ float nes[16 * 10];
#pragma unroll
    for (int d = 0; d < 10; d++) wps[d * 256 + tid] = wp[d * 6144 + col];
    if (tid < 160) nes[tid] = ne[n0 * 10 + tid];
    __syncthreads();
    for (int nn = 0; nn < 16; nn++) {
        float acc = 0.f;
#pragma unroll
        for (int d = 0; d < 10; d++) acc += nes[nn * 10 + d] * wps[d * 256 + tid];
        g_WnH[(n0 + nn) * 6144 + col] = __float2half_rn(acc);
    }
}

// ---------------- K4: REDUX selection (unchanged from R10) -------------------
#define CE(a, b) { if (v[a] < v[b]) { uint64_t _t = v[a]; v[a] = v[b]; v[b] = _t; } }

__global__ __launch_bounds__(256) void k_select(const float* __restrict__ ne) {
    __shared__ uint64_t s_wk[128];
    __shared__ uint64_t s_ck[16];

    int i = blockIdx.x, tid = threadIdx.x, lane = tid & 31, w = tid >> 5;

    float nei[10];
#pragma unroll
    for (int d = 0; d < 10; d++) nei[d] = __ldg(&ne[i * 10 + d]);

    int jbase = w * 256 + lane * 8;
    float acc[8] = {0, 0, 0, 0, 0, 0, 0, 0};
#pragma unroll
    for (int d = 0; d < 10; d++) {
        const float4* rp = (const float4*)&g_neT[d * NN + jbase];
        float4 a0 = rp[0], a1 = rp[1];
        float c = nei[d];
        acc[0] += c * a0.x; acc[1] += c * a0.y; acc[2] += c * a0.z; acc[3] += c * a0.w;
        acc[4] += c * a1.x; acc[5] += c * a1.y; acc[6] += c * a1.z; acc[7] += c * a1.w;
    }
    uint64_t v[8];
#pragma unroll
    for (int q = 0; q < 8; q++)
        v[q] = ((uint64_t)ordkey(acc[q]) << 32) | (uint32_t)(2047 - (jbase + q));

    CE(0,1) CE(2,3) CE(4,5) CE(6,7)
    CE(0,2) CE(1,3) CE(4,6) CE(5,7)
    CE(1,2) CE(5,6) CE(0,4) CE(3,7)
    CE(1,5) CE(2,6)
    CE(1,4) CE(3,6)
    CE(2,4) CE(3,5)
    CE(3,4)

    for (int r = 0; r < 16; r++) {
        uint32_t hi = (uint32_t)(v[0] >> 32);
        uint32_t mx = __reduce_max_sync(0xffffffffu, hi);
        uint32_t lo = (hi == mx) ? (uint32_t)v[0] : 0u;
        uint32_t mlo = __reduce_max_sync(0xffffffffu, lo);
        if (lane == 0) s_wk[w * 16 + r] = ((uint64_t)mx << 32) | mlo;
        if (hi == mx && (uint32_t)v[0] == mlo) {
            v[0] = v[1]; v[1] = v[2]; v[2] = v[3]; v[3] = v[4];
            v[4] = v[5]; v[5] = v[6]; v[6] = v[7]; v[7] = 0ull;
        }
    }
    __syncthreads();

    if (w == 0) {
        uint64_t v[4];
#pragma unroll
        for (int q = 0; q < 4; q++) v[q] = s_wk[q * 32 + lane];
        CE(0,1) CE(2,3) CE(0,2) CE(1,3) CE(1,2)
        for (int r = 0; r < 16; r++) {
            uint32_t hi = (uint32_t)(v[0] >> 32);
            uint32_t mx = __reduce_max_sync(0xffffffffu, hi);
            uint32_t lo = (hi == mx) ? (uint32_t)v[0] : 0u;
            uint32_t mlo = __reduce_max_sync(0xffffffffu, lo);
            if (lane == 0) s_ck[r] = ((uint64_t)mx << 32) | mlo;
            if (hi == mx && (uint32_t)v[0] == mlo) {
                v[0] = v[1]; v[1] = v[2]; v[2] = v[3]; v[3] = 0ull;
            }
        }
    }
    __syncthreads();

    {
        int L = lane & 15;
        int b = w + ((lane & 16) ? 8 : 0);
        uint64_t ck = s_ck[L];
        int   cj = 2047 - (int)(ck & 0x7ffu);
        float cv = ordval((uint32_t)(ck >> 32));

        float s = g_sc[b], at = g_at[b];
        float pre = s * (cv + at);
        float myv = pre > 0.f ? pre : 0.f;
        uint32_t e = (uint32_t)b * 4194304u + (uint32_t)i * 2048u + (uint32_t)cj;
        float key = __fadd_rn(myv, jax_noise(e));

        int half = lane & 16;
        int rank = 0;
#pragma unroll
        for (int kk = 0; kk < 16; kk++) {
            float ok = __shfl_sync(0xffffffffu, key, half + kk);
            rank += (ok > key) || (ok == key && kk < L);
        }
        bool sel = rank < 10;

        float mv = sel ? myv : NEGINF;
#pragma unroll
        for (int off = 8; off; off >>= 1)
            mv = fmaxf(mv, __shfl_xor_sync(0xffffffffu, mv, off));
        float se = sel ? expf(myv - mv) : 0.f;
        float ss = se;
#pragma unroll
        for (int off = 8; off; off >>= 1)
            ss += __shfl_xor_sync(0xffffffffu, ss, off);
        float eu = expf(-mv);
        float Z = ss + 2038.f * eu;
        float unif = eu / Z;

        unsigned mask = __ballot_sync(0xffffffffu, sel);
        unsigned hm = half ? (mask >> 16) : (mask & 0xffffu);
        if (sel) {
            int pos = __popc(hm & ((1u << L) - 1u));
            int base = (b * NN + i) * 10 + pos;
            g_sidx[base] = cj;
            g_w[base] = se / Z - unif;
        }
        if (L == 0) g_unif[b * NN + i] = unif;
    }
}
#undef CE

// ---------------- K5/K7: y = A @ src; pass1 also emits csy partials ----------
__global__ __launch_bounds__(256) void k_spmv(const float* __restrict__ src,
                                              const float* __restrict__ cs,
                                              const float* __restrict__ x,
                                              float* __restrict__ dst,
                                              int pass2, int ncs) {
    __shared__ float sm[256];
    int lane = threadIdx.x & 31, w = threadIdx.x >> 5;
    int r = blockIdx.x * 8 + w;                  // r = b*2048 + n
    int b = r >> 11;
    float csv = 0.f;
    for (int g = 0; g < ncs; g++) csv += cs[(b * ncs + g) * 32 + lane];
    float acc = g_unif[r] * csv;
    const int*   id = g_sidx + r * 10;
    const float* ww = g_w + r * 10;
#pragma unroll
    for (int tt = 0; tt < 10; tt++)
        acc += ww[tt] * src[(b * NN + id[tt]) * 32 + lane];
    if (pass2) acc = 2.f * acc - x[r * 32 + lane];
    dst[r * 32 + lane] = acc;

    if (!pass2) {
        // block partial column-sum of y1 -> slot-spread atomics
        sm[w * 32 + lane] = acc;
        __syncthreads();
        if (w == 0) {
            float s = sm[lane];
#pragma unroll
            for (int q = 1; q < 8; q++) s += sm[q * 32 + lane];
            int slot = blockIdx.x & 31;
            atomicAdd(&g_csy2[(b * 32 + slot) * 32 + lane], s);
        }
    }
}

// ---------------- K8: per-node term + biases (fp16 Wn, float4 inner) ---------
__global__ __launch_bounds__(128) void k_out1(const float* __restrict__ x,
                                              const float* __restrict__ y1,
                                              const float* __restrict__ y2,
                                              const float* __restrict__ ne,
                                              const float* __restrict__ bp,
                                              float* __restrict__ out) {
    int n = blockIdx.x, tid = threadIdx.x;
    __shared__ float sWt[64 * 100];   // [o][k], pad 100 (16B-aligned float4 rows)
    __shared__ float sx[16 * 96];
    __shared__ float sbp[640];
    __shared__ float snerow[10];
    // stage Wn (half2 -> float pair, transposed scatter)
    const uint32_t* wh = (const uint32_t*)(g_WnH + n * 6144);
    for (int m = tid; m < 3072; m += 128) {
        uint32_t pk = wh[m];
        __half2 h2 = *(__half2*)&pk;
        float2 f = __half22float2(h2);
        int e = 2 * m;
        int k = e >> 6, o = e & 63;       // o even
        sWt[o * 100 + k]       = f.x;
        sWt[(o + 1) * 100 + k] = f.y;
    }
    for (int m = tid; m < 1536; m += 128) {
        int b = m / 96, k = m - b * 96;
        const float* src = (k < 32) ? x : (k < 64) ? y1 : y2;
        sx[m] = src[(b * NN + n) * 32 + (k & 31)];
    }
    for (int m = tid; m < 640; m += 128) sbp[m] = bp[m];
    if (tid < 10) snerow[tid] = ne[n * 10 + tid];
    __syncthreads();
    int o = tid & 63, g = tid >> 6;
    float acc[8] = {0, 0, 0, 0, 0, 0, 0, 0};
    for (int k4 = 0; k4 < 24; k4++) {
        float4 wv = *(const float4*)&sWt[o * 100 + k4 * 4];
#pragma unroll
        for (int q = 0; q < 8; q++) {
            float4 xv = *(const float4*)&sx[(g + 2 * q) * 96 + k4 * 4];
            acc[q] += xv.x * wv.x + xv.y * wv.y + xv.z * wv.z + xv.w * wv.w;
        }
    }
    float bn = 0.f;
#pragma unroll
    for (int d = 0; d < 10; d++) bn += snerow[d] * sbp[d * 64 + o];
#pragma unroll
    for (int q = 0; q < 8; q++) {
        int b = g + 2 * q;
        out[((b * NN) + n) * 64 + o] = acc[q] + bn + g_biasB[b * 64 + o];
    }
}

// ---------------- K9: per-batch GEMM term, accumulates into out --------------
__global__ __launch_bounds__(256) void k_out2(const float* __restrict__ x,
                                              const float* __restrict__ y1,
                                              const float* __restrict__ y2,
                                              float* __restrict__ out) {
    int n0 = blockIdx.x * 64, b = blockIdx.y, tid = threadIdx.x;
    __shared__ float sWb[48 * 64];
    __shared__ float sxg[64 * 97];
    {
        const float* srcs[3] = {x, y1, y2};
#pragma unroll
        for (int a = 0; a < 3; a++) {
            const float* s = srcs[a];
            for (int m = tid; m < 2048; m += 256) {
                int rr = m >> 5, c = m & 31;
                sxg[rr * 97 + a * 32 + c] = s[(b * NN + n0 + rr) * 32 + c];
            }
        }
    }
    int o0 = (tid & 15) * 4, tn = tid >> 4;
    float acc[4][4];
#pragma unroll
    for (int rr = 0; rr < 4; rr++)
#pragma unroll
        for (int oo = 0; oo < 4; oo++) acc[rr][oo] = 0.f;

    for (int kc = 0; kc < 2; kc++) {
        __syncthreads();
        for (int m = tid; m < 3072; m += 256)
            sWb[m] = g_Wb[b * 6144 + kc * 3072 + m];
        __syncthreads();
        for (int k = 0; k < 48; k++) {
            float4 wv = *(const float4*)&sWb[k * 64 + o0];
#pragma unroll
            for (int rr = 0; rr < 4; rr++) {
                float xv = sxg[(tn + 16 * rr) * 97 + kc * 48 + k];
                acc[rr][0] += xv * wv.x; acc[rr][1] += xv * wv.y;
                acc[rr][2] += xv * wv.z; acc[rr][3] += xv * wv.w;
            }
        }
    }
#pragma unroll
    for (int rr = 0; rr < 4; rr++) {
        int row = tn + 16 * rr;
        float4* op = (float4*)&out[((b * NN) + (n0 + row)) * 64 + o0];
        float4 cur = *op;
        cur.x += acc[rr][0]; cur.y += acc[rr][1];
        cur.z += acc[rr][2]; cur.w += acc[rr][3];
        *op = cur;
    }
}

// ---------------- launch ------------------------------------------------------
extern "C" void kernel_launch(void* const* d_in, const int* in_sizes, int n_in,
                              void* d_out, int out_size) {
    const float* x  = (const float*)d_in[0];
    const float* ne = (const float*)d_in[1];
    const float* t  = (const float*)d_in[2];
    const float* nt = (const float*)d_in[3];
    const float* p  = (const float*)d_in[4];
    const float* wp = (const float*)d_in[5];
    const float* bp = (const float*)d_in[6];
    float* out = (float*)d_out;

    float *y1, *y2, *csx, *csy2;
    cudaGetSymbolAddress((void**)&y1, g_y1);
    cudaGetSymbolAddress((void**)&y2, g_y2);
    cudaGetSymbolAddress((void**)&csx, g_csx);
    cudaGetSymbolAddress((void**)&csy2, g_csy2);

    k_prep<<<dim3(BSZ, 9), 512>>>(t, nt, p, wp, bp, ne, x);
    k_select<<<NN, 256>>>(ne);
    k_spmv<<<4096, 256>>>(x, csx, x, y1, 0, 8);
    k_spmv<<<4096, 256>>>(y1, csy2, x, y2, 1, 32);
    k_wn<<<dim3(128, 24), 256>>>(ne, wp);
    k_out1<<<NN, 128>>>(x, y1, y2, ne, bp, out);
    k_out2<<<dim3(32, BSZ), 256>>>(x, y1, y2, out);
}